// round 15
// baseline (speedup 1.0000x reference)
#include <cuda_runtime.h>
#include <cstdint>

#define TT   128
#define BLK  128
#define EPB  64          // elements per block: 4 warps x 16

// ---- shared layout (floats) ----
// two weight planes of 440 floats (220 u64): Xw[5k][20j] pairs (200f), Hw (200f), bias (40f)
// even plane @0: {lstm1, lstm2b}; odd plane @440: {lstm2a, 0}
#define PLANE_F 440
#define FC_OFF  880
#define FW1 (FC_OFF)
#define FB1 (FW1+640)
#define FW2 (FB1+32)
#define FB2 (FW2+1024)
#define FW3 (FB2+32)
#define FB3 (FW3+512)
#define FW4 (FB3+16)
#define FB4 (FW4+256)
#define FW5 (FB4+16)
#define FB5 (FW5+80)
#define S_TOTAL (FB5+5)   // 3493 floats = ~14 KB

typedef unsigned long long u64;

__device__ __forceinline__ float tanh_fast(float x) {
    float y;
    asm("tanh.approx.f32 %0, %1;" : "=f"(y) : "f"(x));
    return y;
}
// rows pre-scaled by 0.5 at staging: sigm(a) = fma(tanh(a'), 0.5, 0.5)
__device__ __forceinline__ float sigm_pre(float a_half) {
    return fmaf(tanh_fast(a_half), 0.5f, 0.5f);
}

__device__ __forceinline__ u64 ffma2(u64 a, u64 b, u64 c) {
    u64 d;
    asm("fma.rn.f32x2 %0, %1, %2, %3;" : "=l"(d) : "l"(a), "l"(b), "l"(c));
    return d;
}
__device__ __forceinline__ u64 pack2(float lo, float hi) {
    u64 d;
    asm("mov.b64 %0, {%1, %2};" : "=l"(d) : "f"(lo), "f"(hi));
    return d;
}
__device__ __forceinline__ void unpack2(u64 v, float& lo, float& hi) {
    asm("mov.b64 {%0, %1}, %2;" : "=f"(lo), "=f"(hi) : "l"(v));
}

// Fused body: ONE step of TWO cells packed in f32x2 halves.
// lo cell: input = xb[k];  hi cell: input = nh[k] (shfl'd h2a, one step behind).
// sP (u64*): Xw[100], Hw at +100, bias at +200. All i/f/o rows pre-scaled by 0.5.
__device__ __forceinline__ void body(const u64* __restrict__ sP,
                                     const float* __restrict__ xb,
                                     const float* __restrict__ nh,
                                     u64* __restrict__ hp,
                                     float* __restrict__ hLo,
                                     float* __restrict__ cLo,
                                     float* __restrict__ cHi) {
    u64 g[20];
    {
        const ulonglong2* b2 = reinterpret_cast<const ulonglong2*>(sP + 200);
        #pragma unroll
        for (int q = 0; q < 10; q++) {
            ulonglong2 v = b2[q];
            g[2*q] = v.x; g[2*q+1] = v.y;
        }
    }
    #pragma unroll
    for (int k = 0; k < 5; k++) {
        u64 xm = pack2(xb[k], nh[k]);
        const ulonglong2* w2 = reinterpret_cast<const ulonglong2*>(sP + k * 20);
        #pragma unroll
        for (int q = 0; q < 10; q++) {
            ulonglong2 w = w2[q];
            g[2*q]   = ffma2(w.x, xm, g[2*q]);
            g[2*q+1] = ffma2(w.y, xm, g[2*q+1]);
        }
    }
    #pragma unroll
    for (int k = 0; k < 5; k++) {
        u64 hm = hp[k];     // already packed {hLo, hHi}
        const ulonglong2* u2 = reinterpret_cast<const ulonglong2*>(sP + 100 + k * 20);
        #pragma unroll
        for (int q = 0; q < 10; q++) {
            ulonglong2 u = u2[q];
            g[2*q]   = ffma2(u.x, hm, g[2*q]);
            g[2*q+1] = ffma2(u.y, hm, g[2*q+1]);
        }
    }
    float aL[20], aH[20];
    #pragma unroll
    for (int j = 0; j < 20; j++) unpack2(g[j], aL[j], aH[j]);

    #pragma unroll
    for (int m = 0; m < 5; m++) {
        float igL = sigm_pre(aL[m]);
        float fgL = sigm_pre(aL[5 + m]);
        float ggL = tanh_fast(aL[10 + m]);
        float ogL = sigm_pre(aL[15 + m]);
        float cmL = fmaf(fgL, cLo[m], igL * ggL);
        float hmL = ogL * tanh_fast(cmL);

        float igH = sigm_pre(aH[m]);
        float fgH = sigm_pre(aH[5 + m]);
        float ggH = tanh_fast(aH[10 + m]);
        float ogH = sigm_pre(aH[15 + m]);
        float cmH = fmaf(fgH, cHi[m], igH * ggH);
        float hmH = ogH * tanh_fast(cmH);

        cLo[m] = cmL; cHi[m] = cmH;
        hLo[m] = hmL;
        hp[m] = pack2(hmL, hmH);
    }
}

// Load one 2-timestep chunk (10 floats, 8B-aligned) with LDG.64.
__device__ __forceinline__ void load2(float* dst, const float* src) {
    const float2* s2 = reinterpret_cast<const float2*>(src);
    #pragma unroll
    for (int i = 0; i < 5; i++) {
        float2 v = __ldg(s2 + i);
        dst[2*i+0] = v.x; dst[2*i+1] = v.y;
    }
}

struct Params {
    const float *x1, *x2;
    const float *Wih1, *Whh1, *bih1, *bhh1;
    const float *Wih2a, *Whh2a, *bih2a, *bhh2a;
    const float *Wih2b, *Whh2b, *bih2b, *bhh2b;
    const float *W1, *b1, *W2, *b2, *W3, *b3, *W4, *b4, *W5, *b5;
    float* out;
    int B;
};

__global__ __launch_bounds__(BLK)
void dynrnn_kernel(Params p) {
    __shared__ __align__(16) float s[S_TOTAL];
    const int tid = threadIdx.x;

    // ---- weight staging: packed-pair planes + scalar FC ----
    // sigmoid-gate rows (j<10 i/f, j>=15 o) pre-scaled by 0.5
    {
        for (int i = tid; i < 100; i += BLK) {
            int j = i / 5, k = i % 5;
            float sc = (j < 10 || j >= 15) ? 0.5f : 1.0f;
            int fo = (k * 20 + j) * 2;
            // even plane: {lstm1, lstm2b}
            s[fo]             = p.Wih1[i] * sc;
            s[fo + 1]         = p.Wih2b[i] * sc;
            s[200 + fo]       = p.Whh1[i] * sc;
            s[200 + fo + 1]   = p.Whh2b[i] * sc;
            // odd plane: {lstm2a, 0}
            s[PLANE_F + fo]           = p.Wih2a[i] * sc;
            s[PLANE_F + fo + 1]       = 0.0f;
            s[PLANE_F + 200 + fo]     = p.Whh2a[i] * sc;
            s[PLANE_F + 200 + fo + 1] = 0.0f;
        }
        for (int j = tid; j < 20; j += BLK) {
            float sc = (j < 10 || j >= 15) ? 0.5f : 1.0f;
            s[400 + 2*j]               = (p.bih1[j]  + p.bhh1[j])  * sc;
            s[400 + 2*j + 1]           = (p.bih2b[j] + p.bhh2b[j]) * sc;
            s[PLANE_F + 400 + 2*j]     = (p.bih2a[j] + p.bhh2a[j]) * sc;
            s[PLANE_F + 400 + 2*j + 1] = 0.0f;
        }
        for (int i = tid; i < 640;  i += BLK) s[FW1 + i] = p.W1[i];
        for (int i = tid; i < 32;   i += BLK) s[FB1 + i] = p.b1[i];
        for (int i = tid; i < 1024; i += BLK) s[FW2 + i] = p.W2[i];
        for (int i = tid; i < 32;   i += BLK) s[FB2 + i] = p.b2[i];
        for (int i = tid; i < 512;  i += BLK) s[FW3 + i] = p.W3[i];
        for (int i = tid; i < 16;   i += BLK) s[FB3 + i] = p.b3[i];
        for (int i = tid; i < 256;  i += BLK) s[FW4 + i] = p.W4[i];
        for (int i = tid; i < 16;   i += BLK) s[FB4 + i] = p.b4[i];
        for (int i = tid; i < 80;   i += BLK) s[FW5 + i] = p.W5[i];
        for (int i = tid; i < 5;    i += BLK) s[FB5 + i] = p.b5[i];
    }
    __syncthreads();

    // ---- lane mapping: 2 lanes per element, 16 elements per warp ----
    // even lane: lo=lstm1(e), hi=lstm2b(e)   (hi fed by shfl from odd lane, 1 step behind)
    // odd  lane: lo=lstm2a(e), hi=dummy (zero weights/bias)
    const int l   = tid & 31;
    const int sub = l & 1;
    const int pr  = l >> 1;          // 0..15

    const int e = blockIdx.x * EPB + (tid >> 5) * 16 + pr;
    const bool valid = (e < p.B);
    const int ec = valid ? e : (p.B - 1);

    const bool odd = (sub == 1);
    const float* __restrict__ xp = (odd ? p.x2 : p.x1) + (size_t)ec * (TT * 5);
    const u64* __restrict__ sP = reinterpret_cast<const u64*>(s + (odd ? PLANE_F : 0));

    u64 hp[5];
    float hLo[5], cLo[5], cHi[5], nh[5];
    #pragma unroll
    for (int m = 0; m < 5; m++) {
        hp[m] = 0ull; hLo[m] = 0.0f; cLo[m] = 0.0f; cHi[m] = 0.0f; nh[m] = 0.0f;
    }

    float A[10], Bb[10];  // 2-step x double buffers
    load2(A, xp);         // chunk 0 (steps 0,1)

    #pragma unroll 1
    for (int it = 0; it < 32; it++) {
        load2(Bb, xp + (2 * it + 1) * 10);
        // steps 4it, 4it+1 from A
        body(sP, &A[0], nh, hp, hLo, cLo, cHi);
        #pragma unroll
        for (int j = 0; j < 5; j++) nh[j] = __shfl_down_sync(0xFFFFFFFFu, hLo[j], 1);
        if (it == 0) {
            // discard hi-half warm-up garbage: reset lstm2b state to zero
            #pragma unroll
            for (int m = 0; m < 5; m++) { hp[m] = pack2(hLo[m], 0.0f); cHi[m] = 0.0f; }
        }
        body(sP, &A[5], nh, hp, hLo, cLo, cHi);
        #pragma unroll
        for (int j = 0; j < 5; j++) nh[j] = __shfl_down_sync(0xFFFFFFFFu, hLo[j], 1);

        int ci = 2 * it + 2; if (ci > 63) ci = 63;   // clamped redundant load on last iter
        load2(A, xp + ci * 10);
        // steps 4it+2, 4it+3 from Bb
        body(sP, &Bb[0], nh, hp, hLo, cLo, cHi);
        #pragma unroll
        for (int j = 0; j < 5; j++) nh[j] = __shfl_down_sync(0xFFFFFFFFu, hLo[j], 1);
        body(sP, &Bb[5], nh, hp, hLo, cLo, cHi);
        #pragma unroll
        for (int j = 0; j < 5; j++) nh[j] = __shfl_down_sync(0xFFFFFFFFu, hLo[j], 1);
    }
    // after loop: lo cells done through step 127; hi = lstm2b through step 126;
    // nh = h2a(127) on even lanes; Bb = chunk 63 (steps 126,127)

    // save out1 (lstm1(127)) before the drain body clobbers lo state
    float out1[5];
    #pragma unroll
    for (int m = 0; m < 5; m++) out1[m] = hLo[m];

    // drain: one more body — hi computes lstm2b(127); lo result is discarded
    body(sP, &Bb[5], nh, hp, hLo, cLo, cHi);

    float out2[5];
    #pragma unroll
    for (int m = 0; m < 5; m++) {
        float lo, hi;
        unpack2(hp[m], lo, hi);
        out2[m] = hi;                       // lstm2b(127)
    }

    // ---- gather x2 last from odd lane ----
    float x2l[5];
    #pragma unroll
    for (int j = 0; j < 5; j++) {
        x2l[j] = __shfl_down_sync(0xFFFFFFFFu, Bb[5 + j], 1);
    }

    if (valid && sub == 0) {
        float a0[20];
        #pragma unroll
        for (int j = 0; j < 5; j++) {
            a0[j]      = Bb[5 + j];  // x1 last
            a0[5 + j]  = x2l[j];     // x2 last
            a0[10 + j] = out1[j];    // out1 (lstm1)
            a0[15 + j] = out2[j];    // out2 (lstm2b)
        }
        float a1[32];
        #pragma unroll
        for (int j = 0; j < 32; j++) {
            float acc = s[FB1 + j];
            #pragma unroll
            for (int k = 0; k < 20; k++) acc = fmaf(s[FW1 + j * 20 + k], a0[k], acc);
            a1[j] = fmaxf(acc, 0.0f);
        }
        float a2[32];
        #pragma unroll
        for (int j = 0; j < 32; j++) {
            float acc = s[FB2 + j];
            #pragma unroll
            for (int k = 0; k < 32; k++) acc = fmaf(s[FW2 + j * 32 + k], a1[k], acc);
            a2[j] = fmaxf(acc, 0.0f);
        }
        float a3[16];
        #pragma unroll
        for (int j = 0; j < 16; j++) {
            float acc = s[FB3 + j];
            #pragma unroll
            for (int k = 0; k < 32; k++) acc = fmaf(s[FW3 + j * 32 + k], a2[k], acc);
            a3[j] = fmaxf(acc, 0.0f);
        }
        float a4[16];
        #pragma unroll
        for (int j = 0; j < 16; j++) {
            float acc = s[FB4 + j];
            #pragma unroll
            for (int k = 0; k < 16; k++) acc = fmaf(s[FW4 + j * 16 + k], a3[k], acc);
            a4[j] = fmaxf(acc, 0.0f);
        }
        #pragma unroll
        for (int j = 0; j < 5; j++) {
            float acc = s[FB5 + j];
            #pragma unroll
            for (int k = 0; k < 16; k++) acc = fmaf(s[FW5 + j * 16 + k], a4[k], acc);
            p.out[(size_t)e * 5 + j] = acc;
        }
    }
}

extern "C" void kernel_launch(void* const* d_in, const int* in_sizes, int n_in,
                              void* d_out, int out_size) {
    Params p;
    p.x1    = (const float*)d_in[0];
    p.x2    = (const float*)d_in[1];
    p.Wih1  = (const float*)d_in[2];
    p.Whh1  = (const float*)d_in[3];
    p.bih1  = (const float*)d_in[4];
    p.bhh1  = (const float*)d_in[5];
    p.Wih2a = (const float*)d_in[6];
    p.Whh2a = (const float*)d_in[7];
    p.bih2a = (const float*)d_in[8];
    p.bhh2a = (const float*)d_in[9];
    p.Wih2b = (const float*)d_in[10];
    p.Whh2b = (const float*)d_in[11];
    p.bih2b = (const float*)d_in[12];
    p.bhh2b = (const float*)d_in[13];
    p.W1 = (const float*)d_in[14];  p.b1 = (const float*)d_in[15];
    p.W2 = (const float*)d_in[16];  p.b2 = (const float*)d_in[17];
    p.W3 = (const float*)d_in[18];  p.b3 = (const float*)d_in[19];
    p.W4 = (const float*)d_in[20];  p.b4 = (const float*)d_in[21];
    p.W5 = (const float*)d_in[22];  p.b5 = (const float*)d_in[23];
    p.out = (float*)d_out;
    p.B   = in_sizes[0] / (TT * 5);

    int grid = (p.B + EPB - 1) / EPB;   // 256 blocks for B=16384 -> single wave
    dynrnn_kernel<<<grid, BLK>>>(p);
}

// round 16
// speedup vs baseline: 2.7482x; 2.7482x over previous
#include <cuda_runtime.h>
#include <cstdint>

#define TT   128
#define BLK  128
#define EPB  40          // elements per block: 4 warps x 10
#define RSTRIDE 220      // floats per role block in shared

// ---- shared layout (floats) ----
#define FC_OFF 660
#define FW1 (FC_OFF)
#define FB1 (FW1+640)
#define FW2 (FB1+32)
#define FB2 (FW2+1024)
#define FW3 (FB2+32)
#define FB3 (FW3+512)
#define FW4 (FB3+16)
#define FB4 (FW4+256)
#define FW5 (FB4+16)
#define FB5 (FW5+80)
#define S_TOTAL (FB5+5)   // 3273 floats = ~13.1 KB

typedef unsigned long long u64;

__device__ __forceinline__ float tanh_fast(float x) {
    float y;
    asm("tanh.approx.f32 %0, %1;" : "=f"(y) : "f"(x));
    return y;
}
// rows pre-scaled by 0.5 at staging: sigm(a) = fma(tanh(a'), 0.5, 0.5)
__device__ __forceinline__ float sigm_pre(float a_half) {
    return fmaf(tanh_fast(a_half), 0.5f, 0.5f);
}

__device__ __forceinline__ u64 ffma2(u64 a, u64 b, u64 c) {
    u64 d;
    asm("fma.rn.f32x2 %0, %1, %2, %3;" : "=l"(d) : "l"(a), "l"(b), "l"(c));
    return d;
}
__device__ __forceinline__ u64 bcast2(float x) {
    u64 d;
    asm("mov.b64 %0, {%1, %1};" : "=l"(d) : "f"(x));
    return d;
}
__device__ __forceinline__ void unpack2(u64 v, float& lo, float& hi) {
    asm("mov.b64 {%0, %1}, %2;" : "=f"(lo), "=f"(hi) : "l"(v));
}

// One H=5 LSTM cell step, packed gate math. Bias folded into the k=0 FMA from registers.
// sW: WihT[5][20], WhhT at +100 (i/f/o rows pre-scaled 0.5); bias2: packed pre-scaled bias (regs).
template <bool COMMIT_ALWAYS>
__device__ __forceinline__ void cell(const float* __restrict__ sW,
                                     const u64* __restrict__ bias2,
                                     const float* __restrict__ in,
                                     float* __restrict__ h,
                                     float* __restrict__ c,
                                     bool commit) {
    u64 g[10];
    {
        u64 x0 = bcast2(in[0]);
        const ulonglong2* w2 = reinterpret_cast<const ulonglong2*>(sW);
        #pragma unroll
        for (int q = 0; q < 5; q++) {
            ulonglong2 w = w2[q];
            g[2*q]   = ffma2(w.x, x0, bias2[2*q]);
            g[2*q+1] = ffma2(w.y, x0, bias2[2*q+1]);
        }
    }
    #pragma unroll
    for (int k = 1; k < 5; k++) {
        u64 xk2 = bcast2(in[k]);
        const ulonglong2* w2 = reinterpret_cast<const ulonglong2*>(sW + k * 20);
        #pragma unroll
        for (int q = 0; q < 5; q++) {
            ulonglong2 w = w2[q];
            g[2*q]   = ffma2(w.x, xk2, g[2*q]);
            g[2*q+1] = ffma2(w.y, xk2, g[2*q+1]);
        }
    }
    #pragma unroll
    for (int k = 0; k < 5; k++) {
        u64 hk2 = bcast2(h[k]);
        const ulonglong2* u2 = reinterpret_cast<const ulonglong2*>(sW + 100 + k * 20);
        #pragma unroll
        for (int q = 0; q < 5; q++) {
            ulonglong2 u = u2[q];
            g[2*q]   = ffma2(u.x, hk2, g[2*q]);
            g[2*q+1] = ffma2(u.y, hk2, g[2*q+1]);
        }
    }
    float ga[20];
    #pragma unroll
    for (int q = 0; q < 10; q++) unpack2(g[q], ga[2*q], ga[2*q+1]);

    #pragma unroll
    for (int m = 0; m < 5; m++) {
        float ig = sigm_pre(ga[m]);
        float fg = sigm_pre(ga[5 + m]);
        float gg = tanh_fast(ga[10 + m]);
        float og = sigm_pre(ga[15 + m]);
        float cm = fmaf(fg, c[m], ig * gg);
        float hm = og * tanh_fast(cm);
        if (COMMIT_ALWAYS) {
            c[m] = cm;
            h[m] = hm;
        } else {
            c[m] = commit ? cm : c[m];
            h[m] = commit ? hm : h[m];
        }
    }
}

// Load one 4-timestep chunk (20 floats, 16B-aligned).
__device__ __forceinline__ void load_chunk(float* dst, const float* src) {
    const float4* s4 = reinterpret_cast<const float4*>(src);
    #pragma unroll
    for (int i = 0; i < 5; i++) {
        float4 v = __ldg(s4 + i);
        dst[4*i+0] = v.x; dst[4*i+1] = v.y;
        dst[4*i+2] = v.z; dst[4*i+3] = v.w;
    }
}

struct Params {
    const float *x1, *x2;
    const float *Wih1, *Whh1, *bih1, *bhh1;
    const float *Wih2a, *Whh2a, *bih2a, *bhh2a;
    const float *Wih2b, *Whh2b, *bih2b, *bhh2b;
    const float *W1, *b1, *W2, *b2, *W3, *b3, *W4, *b4, *W5, *b5;
    float* out;
    int B;
};

__global__ __launch_bounds__(BLK, 2)
void dynrnn_kernel(Params p) {
    __shared__ float s[S_TOTAL];
    const int tid = threadIdx.x;

    // ---- cooperative weight staging (transposed LSTM weights, role blocks) ----
    // sigmoid-gate rows (j<10 i/f, j>=15 o) pre-scaled by 0.5
    {
        const float* srcs[6] = { p.Wih1, p.Whh1, p.Wih2a, p.Whh2a, p.Wih2b, p.Whh2b };
        const int    offs[6] = { 0, 100, RSTRIDE, RSTRIDE+100, 2*RSTRIDE, 2*RSTRIDE+100 };
        for (int m = 0; m < 6; m++) {
            const float* W = srcs[m];
            int off = offs[m];
            for (int i = tid; i < 100; i += BLK) {
                int j = i / 5, k = i % 5;
                float sc = (j < 10 || j >= 15) ? 0.5f : 1.0f;
                s[off + k * 20 + j] = W[i] * sc;
            }
        }
        for (int i = tid; i < 20; i += BLK) {
            float sc = (i < 10 || i >= 15) ? 0.5f : 1.0f;
            s[0*RSTRIDE + 200 + i] = (p.bih1[i]  + p.bhh1[i])  * sc;
            s[1*RSTRIDE + 200 + i] = (p.bih2a[i] + p.bhh2a[i]) * sc;
            s[2*RSTRIDE + 200 + i] = (p.bih2b[i] + p.bhh2b[i]) * sc;
        }
        for (int i = tid; i < 640;  i += BLK) s[FW1 + i] = p.W1[i];
        for (int i = tid; i < 32;   i += BLK) s[FB1 + i] = p.b1[i];
        for (int i = tid; i < 1024; i += BLK) s[FW2 + i] = p.W2[i];
        for (int i = tid; i < 32;   i += BLK) s[FB2 + i] = p.b2[i];
        for (int i = tid; i < 512;  i += BLK) s[FW3 + i] = p.W3[i];
        for (int i = tid; i < 16;   i += BLK) s[FB3 + i] = p.b3[i];
        for (int i = tid; i < 256;  i += BLK) s[FW4 + i] = p.W4[i];
        for (int i = tid; i < 16;   i += BLK) s[FB4 + i] = p.b4[i];
        for (int i = tid; i < 80;   i += BLK) s[FW5 + i] = p.W5[i];
        for (int i = tid; i < 5;    i += BLK) s[FB5 + i] = p.b5[i];
    }
    __syncthreads();

    // ---- lane/role mapping: 3 lanes per element, 10 elements per warp ----
    const int l   = tid & 31;
    const int grp = l / 3;           // 0..9
    const int r   = l - 3 * grp;     // 0: lstm1, 1: lstm2a, 2: lstm2b
    const bool lane_ok = (l < 30);

    const int e = blockIdx.x * EPB + (tid >> 5) * 10 + grp;
    const bool valid = lane_ok && (e < p.B);
    const int ec = (e < p.B) ? e : (p.B - 1);

    const float* __restrict__ xp = ((r == 1) ? p.x2 : p.x1) + (size_t)ec * (TT * 5);
    const float* __restrict__ sW = s + r * RSTRIDE;
    const bool isr2 = (r == 2);

    // hoist pre-scaled fused bias into registers (packed pairs)
    u64 bias2[10];
    {
        const ulonglong2* b2 = reinterpret_cast<const ulonglong2*>(sW + 200);
        #pragma unroll
        for (int q = 0; q < 5; q++) {
            ulonglong2 v = b2[q];
            bias2[2*q] = v.x; bias2[2*q+1] = v.y;
        }
    }

    float h[5], c[5], nh[5];
    #pragma unroll
    for (int m = 0; m < 5; m++) { h[m] = 0.0f; c[m] = 0.0f; nh[m] = 0.0f; }

    float A[20], Bb[20];
    load_chunk(A, xp);

    // ---- peeled it=0 (steps 0..7): commit-select only here ----
    {
        load_chunk(Bb, xp + 20);
        #pragma unroll
        for (int tl = 0; tl < 4; tl++) {
            float in[5];
            #pragma unroll
            for (int j = 0; j < 5; j++) in[j] = isr2 ? nh[j] : A[tl * 5 + j];
            bool commit = !(isr2 && (tl == 0));
            cell<false>(sW, bias2, in, h, c, commit);
            #pragma unroll
            for (int j = 0; j < 5; j++) nh[j] = __shfl_up_sync(0xFFFFFFFFu, h[j], 1);
        }
        load_chunk(A, xp + 40);
        #pragma unroll
        for (int tl = 0; tl < 4; tl++) {
            float in[5];
            #pragma unroll
            for (int j = 0; j < 5; j++) in[j] = isr2 ? nh[j] : Bb[tl * 5 + j];
            cell<true>(sW, bias2, in, h, c, true);
            #pragma unroll
            for (int j = 0; j < 5; j++) nh[j] = __shfl_up_sync(0xFFFFFFFFu, h[j], 1);
        }
    }

    // ---- main loop it=1..15: no commit selects ----
    #pragma unroll 1
    for (int it = 1; it < 16; it++) {
        load_chunk(Bb, xp + (2 * it + 1) * 20);
        #pragma unroll
        for (int tl = 0; tl < 4; tl++) {
            float in[5];
            #pragma unroll
            for (int j = 0; j < 5; j++) in[j] = isr2 ? nh[j] : A[tl * 5 + j];
            cell<true>(sW, bias2, in, h, c, true);
            #pragma unroll
            for (int j = 0; j < 5; j++) nh[j] = __shfl_up_sync(0xFFFFFFFFu, h[j], 1);
        }
        int ci = 2 * it + 2; if (ci > 31) ci = 31;
        load_chunk(A, xp + ci * 20);
        #pragma unroll
        for (int tl = 0; tl < 4; tl++) {
            float in[5];
            #pragma unroll
            for (int j = 0; j < 5; j++) in[j] = isr2 ? nh[j] : Bb[tl * 5 + j];
            cell<true>(sW, bias2, in, h, c, true);
            #pragma unroll
            for (int j = 0; j < 5; j++) nh[j] = __shfl_up_sync(0xFFFFFFFFu, h[j], 1);
        }
    }

    // role-2 drains the pipeline: final step consumes h2a(127)
    if (isr2) {
        cell<true>(sW, bias2, nh, h, c, true);
    }

    // ---- gather results onto role-0 lanes ----
    // last timestep inputs live in Bb[15..19] (chunk 31 = steps 124..127)
    float x2l[5], o2[5];
    #pragma unroll
    for (int j = 0; j < 5; j++) {
        x2l[j] = __shfl_down_sync(0xFFFFFFFFu, Bb[15 + j], 1);  // from role 1 (x2 last)
        o2[j]  = __shfl_down_sync(0xFFFFFFFFu, h[j], 2);        // from role 2 (out2)
    }

    if (valid && r == 0) {
        float a0[20];
        #pragma unroll
        for (int j = 0; j < 5; j++) {
            a0[j]      = Bb[15 + j];
            a0[5 + j]  = x2l[j];
            a0[10 + j] = h[j];
            a0[15 + j] = o2[j];
        }
        float a1[32];
        #pragma unroll
        for (int j = 0; j < 32; j++) {
            float acc = s[FB1 + j];
            #pragma unroll
            for (int k = 0; k < 20; k++) acc = fmaf(s[FW1 + j * 20 + k], a0[k], acc);
            a1[j] = fmaxf(acc, 0.0f);
        }
        float a2[32];
        #pragma unroll
        for (int j = 0; j < 32; j++) {
            float acc = s[FB2 + j];
            #pragma unroll
            for (int k = 0; k < 32; k++) acc = fmaf(s[FW2 + j * 32 + k], a1[k], acc);
            a2[j] = fmaxf(acc, 0.0f);
        }
        float a3[16];
        #pragma unroll
        for (int j = 0; j < 16; j++) {
            float acc = s[FB3 + j];
            #pragma unroll
            for (int k = 0; k < 32; k++) acc = fmaf(s[FW3 + j * 32 + k], a2[k], acc);
            a3[j] = fmaxf(acc, 0.0f);
        }
        float a4[16];
        #pragma unroll
        for (int j = 0; j < 16; j++) {
            float acc = s[FB4 + j];
            #pragma unroll
            for (int k = 0; k < 16; k++) acc = fmaf(s[FW4 + j * 16 + k], a3[k], acc);
            a4[j] = fmaxf(acc, 0.0f);
        }
        #pragma unroll
        for (int j = 0; j < 5; j++) {
            float acc = s[FB5 + j];
            #pragma unroll
            for (int k = 0; k < 16; k++) acc = fmaf(s[FW5 + j * 16 + k], a4[k], acc);
            p.out[(size_t)e * 5 + j] = acc;
        }
    }
}

extern "C" void kernel_launch(void* const* d_in, const int* in_sizes, int n_in,
                              void* d_out, int out_size) {
    Params p;
    p.x1    = (const float*)d_in[0];
    p.x2    = (const float*)d_in[1];
    p.Wih1  = (const float*)d_in[2];
    p.Whh1  = (const float*)d_in[3];
    p.bih1  = (const float*)d_in[4];
    p.bhh1  = (const float*)d_in[5];
    p.Wih2a = (const float*)d_in[6];
    p.Whh2a = (const float*)d_in[7];
    p.bih2a = (const float*)d_in[8];
    p.bhh2a = (const float*)d_in[9];
    p.Wih2b = (const float*)d_in[10];
    p.Whh2b = (const float*)d_in[11];
    p.bih2b = (const float*)d_in[12];
    p.bhh2b = (const float*)d_in[13];
    p.W1 = (const float*)d_in[14];  p.b1 = (const float*)d_in[15];
    p.W2 = (const float*)d_in[16];  p.b2 = (const float*)d_in[17];
    p.W3 = (const float*)d_in[18];  p.b3 = (const float*)d_in[19];
    p.W4 = (const float*)d_in[20];  p.b4 = (const float*)d_in[21];
    p.W5 = (const float*)d_in[22];  p.b5 = (const float*)d_in[23];
    p.out = (float*)d_out;
    p.B   = in_sizes[0] / (TT * 5);

    int grid = (p.B + EPB - 1) / EPB;   // 410 blocks for B=16384
    dynrnn_kernel<<<grid, BLK>>>(p);
}